// round 15
// baseline (speedup 1.0000x reference)
#include <cuda_runtime.h>
#include <cuda_fp16.h>
#include <mma.h>
#include <cstdint>

using namespace nvcuda;

// Fused 2-layer GCN (chain graph), wmma fp16 3-term split.
// R11: single 8-warp group per SM (256 thr), tile = 124 nodes (128 MMA rows).
//  Bigger warp tiles cut fragment-load redundancy: MMA1 32x64 (A-red2,B-red4),
//  MMA2 32x32 (A-red2,B-red4): frag bytes/node -30%. Resident weights,
//  chunked stencil2/MMA2, cross-tile x prefetch as before.

#define NTHREADS 256
#define OUT_TILE 124
#define XROWS    130     // x nodes base-2 .. base+127
#define HROWS    128     // h nodes base-1 .. base+126

#define LDA1  72
#define LDW1  136
#define LDW2  72
#define LDH   130
#define LDX   68
#define LDA2C 40
#define LDO   68

#define OFF_W1H 0
#define OFF_W1L 17408
#define OFF_W2H 34816
#define OFF_W2L 53248
#define OFF_BB1 71680
#define OFF_BB2 75776
#define OFF_ONES 77824
#define G_A    78336     // A1h[128][72]=18432, A1l@+18432 (36864); chunk bufs
                         // overlay: buf b @ b*20480 (h@0,l@+10240); region 40960
#define G_SH   119296    // sH[128][130] f32 = 66560 ; sOut overlays
#define G_SXS  185856    // sXs[130][68] f32 = 35360
#define G_SDV  221216    // 2 x 132 floats (528B each)
#define SMEM_BYTES 222272

__device__ __align__(256) __half g_W1ph[64 * 136];
__device__ __align__(256) __half g_W1pl[64 * 136];
__device__ __align__(256) __half g_W2ph[128 * 72];
__device__ __align__(256) __half g_W2pl[128 * 72];
__device__ __align__(256) __half g_Bb1[16 * 128];
__device__ __align__(256) __half g_Bb2[16 * 64];

__device__ __forceinline__ void split_h(float v, __half& hi, __half& lo) {
    hi = __float2half_rn(v);
    lo = __float2half_rn(v - __half2float(hi));
}
__device__ __forceinline__ uint32_t smem_u32(const void* p) {
    uint32_t a;
    asm("{ .reg .u64 t; cvta.to.shared.u64 t, %1; cvt.u32.u64 %0, t; }"
        : "=r"(a) : "l"(p));
    return a;
}
#define CP16(dst, src, nbytes) \
    asm volatile("cp.async.cg.shared.global [%0], [%1], 16, %2;" \
                 :: "r"(dst), "l"(src), "r"((uint32_t)(nbytes)))
#define CP_COMMIT() asm volatile("cp.async.commit_group;")
#define CP_WAIT0()  asm volatile("cp.async.wait_group 0;")

__global__ void gcn_prep(const float* __restrict__ W1,
                         const float* __restrict__ b1,
                         const float* __restrict__ W2,
                         const float* __restrict__ b2)
{
    int tid = blockIdx.x * blockDim.x + threadIdx.x;
    int nt = gridDim.x * blockDim.x;
    for (int e = tid; e < 64 * 136; e += nt) {
        int r = e / 136, c = e % 136;
        __half hi = __float2half_rn(0.f), lo = hi;
        if (c < 128) split_h(W1[r * 128 + c], hi, lo);
        g_W1ph[e] = hi; g_W1pl[e] = lo;
    }
    for (int e = tid; e < 128 * 72; e += nt) {
        int r = e / 72, c = e % 72;
        __half hi = __float2half_rn(0.f), lo = hi;
        if (c < 64) split_h(W2[r * 64 + c], hi, lo);
        g_W2ph[e] = hi; g_W2pl[e] = lo;
    }
    for (int e = tid; e < 16 * 128; e += nt) {
        int r = e >> 7, c = e & 127;
        __half hi, lo; split_h(b1[c], hi, lo);
        g_Bb1[e] = (r == 0) ? hi : (r == 1) ? lo : __float2half_rn(0.f);
    }
    for (int e = tid; e < 16 * 64; e += nt) {
        int r = e >> 6, c = e & 63;
        __half hi, lo; split_h(b2[c], hi, lo);
        g_Bb2[e] = (r == 0) ? hi : (r == 1) ? lo : __float2half_rn(0.f);
    }
}

__global__ __launch_bounds__(NTHREADS, 1)
void gcn_main(const float* __restrict__ x, float* __restrict__ out, int N)
{
    extern __shared__ char smem[];
    const uint32_t sb = smem_u32(smem);
    const int tid = threadIdx.x;
    const int wid = tid >> 5;

    // ---------- one-time: stage W / biases / ones ----------
    for (int e = tid; e < 1088; e += NTHREADS)
        CP16(sb + OFF_W1H + e * 16, (const char*)g_W1ph + e * 16, 16);
    for (int e = tid; e < 1088; e += NTHREADS)
        CP16(sb + OFF_W1L + e * 16, (const char*)g_W1pl + e * 16, 16);
    for (int e = tid; e < 1152; e += NTHREADS)
        CP16(sb + OFF_W2H + e * 16, (const char*)g_W2ph + e * 16, 16);
    for (int e = tid; e < 1152; e += NTHREADS)
        CP16(sb + OFF_W2L + e * 16, (const char*)g_W2pl + e * 16, 16);
    for (int e = tid; e < 256; e += NTHREADS)
        CP16(sb + OFF_BB1 + e * 16, (const char*)g_Bb1 + e * 16, 16);
    for (int e = tid; e < 128; e += NTHREADS)
        CP16(sb + OFF_BB2 + e * 16, (const char*)g_Bb2 + e * 16, 16);
    ((__half*)(smem + OFF_ONES))[tid] =
        __float2half_rn(((tid & 15) < 2) ? 1.0f : 0.0f);

    __half* W1h = (__half*)(smem + OFF_W1H);
    __half* W1l = (__half*)(smem + OFF_W1L);
    __half* W2h = (__half*)(smem + OFF_W2H);
    __half* W2l = (__half*)(smem + OFF_W2L);
    __half* sBb1 = (__half*)(smem + OFF_BB1);
    __half* sBb2 = (__half*)(smem + OFF_BB2);
    __half* sOnes = (__half*)(smem + OFF_ONES);
    __half* A1h = (__half*)(smem + G_A);
    __half* A1l = (__half*)(smem + G_A + 18432);
    float* sH   = (float*)(smem + G_SH);
    float* sOut = (float*)(smem + G_SH);
    float* sXs  = (float*)(smem + G_SXS);

    const long long ntiles = ((long long)N + OUT_TILE - 1) / OUT_TILE;
    long long tile = blockIdx.x;
    int p = 0;

    // ---------- prologue: first tile's x + dinv ----------
    if (tile < ntiles) {
        long long base = tile * OUT_TILE;
        for (int e = tid; e < XROWS * 16; e += NTHREADS) {
            int t = e >> 4, q = e & 15;
            long long node = base - 2 + t;
            bool ok = (node >= 0 && node < (long long)N);
            const float* src = ok ? (x + node * 64 + q * 4) : x;
            CP16(sb + G_SXS + (uint32_t)(t * 272 + q * 16), src, ok ? 16 : 0);
        }
        if (tid < 132) {
            long long node = base - 2 + tid;
            float v = 0.0f;
            if (node >= 0 && node < (long long)N)
                v = (node == 0 || node == (long long)N - 1)
                    ? 0.70710678118654752f : 0.57735026918962576f;
            ((float*)(smem + G_SDV))[tid] = v;
        }
    }
    CP_COMMIT();
    CP_WAIT0();
    __syncthreads();

    // ---------- persistent tile loop ----------
    for (; tile < ntiles; tile += gridDim.x) {
        const long long base = tile * OUT_TILE;
        float* sdv = (float*)(smem + G_SDV + p * 528);

        // ---- stencil1 (4 rows/task) -> A1 [128][64] ----
        for (int e = tid; e < 32 * 32; e += NTHREADS) {
            int j0 = (e >> 5) * 4, kp = (e & 31) * 2;
            float2 v[6];
            #pragma unroll
            for (int i = 0; i < 6; i++)           // j0+5 <= 129 in-bounds
                v[i] = *(float2*)&sXs[(j0 + i) * LDX + kp];
            #pragma unroll
            for (int rr = 0; rr < 4; rr++) {
                int j = j0 + rr;
                float d0 = sdv[j], d1 = sdv[j + 1], d2 = sdv[j + 2];
                float ax = d1 * (d0 * v[rr].x + d1 * v[rr + 1].x + d2 * v[rr + 2].x);
                float ay = d1 * (d0 * v[rr].y + d1 * v[rr + 1].y + d2 * v[rr + 2].y);
                __half hx, lx, hy, ly;
                split_h(ax, hx, lx);
                split_h(ay, hy, ly);
                *(__half2*)&A1h[j * LDA1 + kp] = __halves2half2(hx, hy);
                *(__half2*)&A1l[j * LDA1 + kp] = __halves2half2(lx, ly);
            }
        }
        __syncthreads();

        // ---- prefetch next tile's x + dinv ----
        {
            long long nt2 = tile + gridDim.x;
            if (nt2 < ntiles) {
                long long nbase = nt2 * OUT_TILE;
                for (int e = tid; e < XROWS * 16; e += NTHREADS) {
                    int t = e >> 4, q = e & 15;
                    long long node = nbase - 2 + t;
                    bool ok = (node >= 0 && node < (long long)N);
                    const float* src = ok ? (x + node * 64 + q * 4) : x;
                    CP16(sb + G_SXS + (uint32_t)(t * 272 + q * 16), src, ok ? 16 : 0);
                }
                if (tid < 132) {
                    long long node = nbase - 2 + tid;
                    float v = 0.0f;
                    if (node >= 0 && node < (long long)N)
                        v = (node == 0 || node == (long long)N - 1)
                            ? 0.70710678118654752f : 0.57735026918962576f;
                    ((float*)(smem + G_SDV + (p ^ 1) * 528))[tid] = v;
                }
            }
            CP_COMMIT();
        }

        // ---- MMA1: sH[128][128] = relu(A1 @ W1 + b1) ; warp tile 32x64 ----
        {
            const int rg = wid >> 1, cg = wid & 1;   // 4 rowgroups x 2 colgroups
            wmma::fragment<wmma::matrix_a, 16, 16, 16, __half, wmma::row_major> ah, al;
            wmma::fragment<wmma::matrix_b, 16, 16, 16, __half, wmma::row_major> bh[4], bl[4];
            wmma::fragment<wmma::accumulator, 16, 16, 16, float> acc[2][4];
            #pragma unroll
            for (int r = 0; r < 2; r++)
                #pragma unroll
                for (int c = 0; c < 4; c++) wmma::fill_fragment(acc[r][c], 0.0f);

            wmma::load_matrix_sync(ah, sOnes, 16);
            #pragma unroll
            for (int c = 0; c < 4; c++)
                wmma::load_matrix_sync(bh[c], sBb1 + (cg * 4 + c) * 16, 128);
            #pragma unroll
            for (int r = 0; r < 2; r++)
                #pragma unroll
                for (int c = 0; c < 4; c++)
                    wmma::mma_sync(acc[r][c], ah, bh[c], acc[r][c]);

            #pragma unroll
            for (int k = 0; k < 4; k++) {
                #pragma unroll
                for (int c = 0; c < 4; c++) {
                    wmma::load_matrix_sync(bh[c], W1h + (k * 16) * LDW1 + (cg * 4 + c) * 16, LDW1);
                    wmma::load_matrix_sync(bl[c], W1l + (k * 16) * LDW1 + (cg * 4 + c) * 16, LDW1);
                }
                #pragma unroll
                for (int r = 0; r < 2; r++) {
                    wmma::load_matrix_sync(ah, A1h + ((rg * 2 + r) * 16) * LDA1 + k * 16, LDA1);
                    wmma::load_matrix_sync(al, A1l + ((rg * 2 + r) * 16) * LDA1 + k * 16, LDA1);
                    #pragma unroll
                    for (int c = 0; c < 4; c++) {
                        wmma::mma_sync(acc[r][c], ah, bh[c], acc[r][c]);
                        wmma::mma_sync(acc[r][c], ah, bl[c], acc[r][c]);
                        wmma::mma_sync(acc[r][c], al, bh[c], acc[r][c]);
                    }
                }
            }
            #pragma unroll
            for (int r = 0; r < 2; r++)
                #pragma unroll
                for (int c = 0; c < 4; c++) {
                    #pragma unroll
                    for (int i = 0; i < acc[r][c].num_elements; i++)
                        acc[r][c].x[i] = fmaxf(acc[r][c].x[i], 0.0f);
                    wmma::store_matrix_sync(
                        sH + ((rg * 2 + r) * 16) * LDH + (cg * 4 + c) * 16,
                        acc[r][c], LDH, wmma::mem_row_major);
                }
        }
        __syncthreads();    // sH ready; A1 dead (chunk bufs may overwrite)

        // ---- stencil2 chunk producer (all 256 threads, 2 iters) ----
        auto stencil2_chunk = [&](int c, int b) {
            __half* bufh = (__half*)(smem + G_A + b * 20480);
            __half* bufl = (__half*)(smem + G_A + b * 20480 + 10240);
            int kc = c * 32;
            #pragma unroll
            for (int it = 0; it < 2; it++) {
                int task = tid + it * 256;           // 0..511
                int r0 = (task >> 4) * 4, kp = (task & 15) * 2;
                float2 v[6];
                #pragma unroll
                for (int i = 0; i < 6; i++)
                    v[i] = (r0 + i <= 127) ? *(float2*)&sH[(r0 + i) * LDH + kc + kp]
                                           : make_float2(0.f, 0.f);
                #pragma unroll
                for (int rr = 0; rr < 4; rr++) {
                    int r = r0 + rr;
                    float zx = 0.f, zy = 0.f;
                    if (r <= 123) {
                        float d1 = sdv[r + 1], d2 = sdv[r + 2], d3 = sdv[r + 3];
                        zx = d2 * (d1 * v[rr].x + d2 * v[rr + 1].x + d3 * v[rr + 2].x);
                        zy = d2 * (d1 * v[rr].y + d2 * v[rr + 1].y + d3 * v[rr + 2].y);
                    }
                    __half hx, lx, hy, ly;
                    split_h(zx, hx, lx);
                    split_h(zy, hy, ly);
                    *(__half2*)&bufh[r * LDA2C + kp] = __halves2half2(hx, hy);
                    *(__half2*)&bufl[r * LDA2C + kp] = __halves2half2(lx, ly);
                }
            }
        };

        // ---- chunk-pipelined stencil2 / MMA2 ; warp tile 32x32 ----
        wmma::fragment<wmma::accumulator, 16, 16, 16, float> acc2[2][2];
        const int rs = wid >> 1, cs = wid & 1;   // 4 rowgroups x 2 colgroups
        {
            #pragma unroll
            for (int r = 0; r < 2; r++)
                #pragma unroll
                for (int c = 0; c < 2; c++) wmma::fill_fragment(acc2[r][c], 0.0f);
            wmma::fragment<wmma::matrix_a, 16, 16, 16, __half, wmma::row_major> aon;
            wmma::fragment<wmma::matrix_b, 16, 16, 16, __half, wmma::row_major> bb;
            wmma::load_matrix_sync(aon, sOnes, 16);
            #pragma unroll
            for (int c = 0; c < 2; c++) {
                wmma::load_matrix_sync(bb, sBb2 + (cs * 2 + c) * 16, 64);
                #pragma unroll
                for (int r = 0; r < 2; r++)
                    wmma::mma_sync(acc2[r][c], aon, bb, acc2[r][c]);
            }
        }

        stencil2_chunk(0, 0);
        __syncthreads();

        #pragma unroll
        for (int c = 0; c < 4; c++) {
            if (c < 3) stencil2_chunk(c + 1, (c + 1) & 1);
            {
                __half* bufh = (__half*)(smem + G_A + (c & 1) * 20480);
                __half* bufl = (__half*)(smem + G_A + (c & 1) * 20480 + 10240);
                wmma::fragment<wmma::matrix_a, 16, 16, 16, __half, wmma::row_major> ah, al;
                wmma::fragment<wmma::matrix_b, 16, 16, 16, __half, wmma::row_major> bh, bl;
                #pragma unroll
                for (int s = 0; s < 2; s++) {
                    #pragma unroll
                    for (int cc = 0; cc < 2; cc++) {
                        wmma::load_matrix_sync(bh, W2h + (c * 32 + s * 16) * LDW2 + (cs * 2 + cc) * 16, LDW2);
                        wmma::load_matrix_sync(bl, W2l + (c * 32 + s * 16) * LDW2 + (cs * 2 + cc) * 16, LDW2);
                        #pragma unroll
                        for (int r = 0; r < 2; r++) {
                            wmma::load_matrix_sync(ah, bufh + ((rs * 2 + r) * 16) * LDA2C + s * 16, LDA2C);
                            wmma::load_matrix_sync(al, bufl + ((rs * 2 + r) * 16) * LDA2C + s * 16, LDA2C);
                            wmma::mma_sync(acc2[r][cc], ah, bh, acc2[r][cc]);
                            wmma::mma_sync(acc2[r][cc], ah, bl, acc2[r][cc]);
                            wmma::mma_sync(acc2[r][cc], al, bh, acc2[r][cc]);
                        }
                    }
                }
            }
            if (c == 3) CP_WAIT0();     // next-tile x landed
            __syncthreads();
        }

        // ---- store: rows <112 direct; rows 112..123 staged ----
        if (base + OUT_TILE <= (long long)N) {
            #pragma unroll
            for (int r = 0; r < 2; r++) {
                int row0 = rs * 32 + r * 16;
                #pragma unroll
                for (int cc = 0; cc < 2; cc++) {
                    int col0 = (cs * 2 + cc) * 16;
                    if (row0 < 112)
                        wmma::store_matrix_sync(out + (base + row0) * 64 + col0,
                                                acc2[r][cc], 64, wmma::mem_row_major);
                    else
                        wmma::store_matrix_sync(sOut + col0, acc2[r][cc], LDO,
                                                wmma::mem_row_major);
                }
            }
            __syncthreads();
            for (int e = tid; e < 12 * 16; e += NTHREADS) {
                int r = e >> 4, q = e & 15;
                *(float4*)(out + (base + 112 + r) * 64 + q * 4) =
                    *(float4*)&sOut[r * LDO + q * 4];
            }
        } else {
            // edge tile: stage all 128 rows, guarded copy of 124
            #pragma unroll
            for (int r = 0; r < 2; r++)
                #pragma unroll
                for (int cc = 0; cc < 2; cc++)
                    wmma::store_matrix_sync(
                        sOut + (rs * 32 + r * 16) * LDO + (cs * 2 + cc) * 16,
                        acc2[r][cc], LDO, wmma::mem_row_major);
            __syncthreads();
            for (int e = tid; e < 124 * 16; e += NTHREADS) {
                int r = e >> 4, q = e & 15;
                long long node = base + r;
                if (node < (long long)N)
                    *(float4*)(out + node * 64 + q * 4) =
                        *(float4*)&sOut[r * LDO + q * 4];
            }
        }
        __syncthreads();    // sOut/sH reads done before next iter overwrites
        p ^= 1;
    }
}

extern "C" void kernel_launch(void* const* d_in, const int* in_sizes, int n_in,
                              void* d_out, int out_size)
{
    const float* x  = (const float*)d_in[0];
    const float* W1 = (const float*)d_in[2];
    const float* b1 = (const float*)d_in[3];
    const float* W2 = (const float*)d_in[4];
    const float* b2 = (const float*)d_in[5];
    float* out = (float*)d_out;

    int N = in_sizes[0] / 64;

    int dev = 0, sms = 148;
    cudaGetDevice(&dev);
    cudaDeviceGetAttribute(&sms, cudaDevAttrMultiProcessorCount, dev);

    gcn_prep<<<32, 256>>>(W1, b1, W2, b2);

    cudaFuncSetAttribute(gcn_main,
                         cudaFuncAttributeMaxDynamicSharedMemorySize,
                         SMEM_BYTES);
    gcn_main<<<sms, NTHREADS, SMEM_BYTES>>>(x, out, N);
}

// round 16
// speedup vs baseline: 1.2176x; 1.2176x over previous
#include <cuda_runtime.h>
#include <cuda_fp16.h>
#include <mma.h>
#include <cstdint>

using namespace nvcuda;

// Fused 2-layer GCN (chain graph), wmma fp16 3-term split.
// R16 = R9 (best: dual 8-warp groups, OUT_TILE=62, resident weights) +
//   float4 stencils (half the LDS instr count), LDH 130->132 for 16B
//   alignment, 8-byte split stores. Structure otherwise identical to R9.

#define NTHREADS 512
#define OUT_TILE 62
#define XROWS    66
#define HROWS    64

#define LDA1  72
#define LDW1  136
#define LDW2  72
#define LDH   132   // fp32; 528B rows (16B-aligned for float4)
#define LDX   68    // fp32; 272B rows (16B-aligned)
#define LDA2C 40
#define LDO   68

#define OFF_W1H 0
#define OFF_W1L 17408
#define OFF_W2H 34816
#define OFF_W2L 53248
#define OFF_BB1 71680
#define OFF_BB2 75776
#define OFF_ONES 77824
#define OFF_GRP  78336
#define G_A    0        // A1h@0 (9216), A1l@9216 ; chunk bufs b@b*10240 (h,l@+5120)
#define G_SH   20480    // sH[64][132] f32 = 33792 ; sOut overlays
#define G_SXS  54272    // sXs[66][68] f32 = 17952
#define G_SDV  72224    // 2 x 288
#define GRP_BYTES 72800
#define SMEM_BYTES (OFF_GRP + 2 * GRP_BYTES)   // 223936

__device__ __align__(256) __half g_W1ph[64 * 136];
__device__ __align__(256) __half g_W1pl[64 * 136];
__device__ __align__(256) __half g_W2ph[128 * 72];
__device__ __align__(256) __half g_W2pl[128 * 72];
__device__ __align__(256) __half g_Bb1[16 * 128];
__device__ __align__(256) __half g_Bb2[16 * 64];

__device__ __forceinline__ void split_h(float v, __half& hi, __half& lo) {
    hi = __float2half_rn(v);
    lo = __float2half_rn(v - __half2float(hi));
}
__device__ __forceinline__ uint32_t smem_u32(const void* p) {
    uint32_t a;
    asm("{ .reg .u64 t; cvta.to.shared.u64 t, %1; cvt.u32.u64 %0, t; }"
        : "=r"(a) : "l"(p));
    return a;
}
// split 4 floats -> two 8B packed (hi, lo) values
__device__ __forceinline__ void split4_pack(float4 z, uint2& phi, uint2& plo) {
    __half hx, lx, hy, ly, hz, lz, hw, lw;
    split_h(z.x, hx, lx); split_h(z.y, hy, ly);
    split_h(z.z, hz, lz); split_h(z.w, hw, lw);
    __half2 h01 = __halves2half2(hx, hy), h23 = __halves2half2(hz, hw);
    __half2 l01 = __halves2half2(lx, ly), l23 = __halves2half2(lz, lw);
    phi = make_uint2(*(uint32_t*)&h01, *(uint32_t*)&h23);
    plo = make_uint2(*(uint32_t*)&l01, *(uint32_t*)&l23);
}
#define CP16(dst, src, nbytes) \
    asm volatile("cp.async.cg.shared.global [%0], [%1], 16, %2;" \
                 :: "r"(dst), "l"(src), "r"((uint32_t)(nbytes)))
#define CP_COMMIT() asm volatile("cp.async.commit_group;")
#define CP_WAIT0()  asm volatile("cp.async.wait_group 0;")
#define GBAR() asm volatile("bar.sync %0, %1;" :: "r"(grp + 1), "r"(256) : "memory")

__global__ void gcn_prep(const float* __restrict__ W1,
                         const float* __restrict__ b1,
                         const float* __restrict__ W2,
                         const float* __restrict__ b2)
{
    int tid = blockIdx.x * blockDim.x + threadIdx.x;
    int nt = gridDim.x * blockDim.x;
    for (int e = tid; e < 64 * 136; e += nt) {
        int r = e / 136, c = e % 136;
        __half hi = __float2half_rn(0.f), lo = hi;
        if (c < 128) split_h(W1[r * 128 + c], hi, lo);
        g_W1ph[e] = hi; g_W1pl[e] = lo;
    }
    for (int e = tid; e < 128 * 72; e += nt) {
        int r = e / 72, c = e % 72;
        __half hi = __float2half_rn(0.f), lo = hi;
        if (c < 64) split_h(W2[r * 64 + c], hi, lo);
        g_W2ph[e] = hi; g_W2pl[e] = lo;
    }
    for (int e = tid; e < 16 * 128; e += nt) {
        int r = e >> 7, c = e & 127;
        __half hi, lo; split_h(b1[c], hi, lo);
        g_Bb1[e] = (r == 0) ? hi : (r == 1) ? lo : __float2half_rn(0.f);
    }
    for (int e = tid; e < 16 * 64; e += nt) {
        int r = e >> 6, c = e & 63;
        __half hi, lo; split_h(b2[c], hi, lo);
        g_Bb2[e] = (r == 0) ? hi : (r == 1) ? lo : __float2half_rn(0.f);
    }
}

__global__ __launch_bounds__(NTHREADS, 1)
void gcn_main(const float* __restrict__ x, float* __restrict__ out, int N)
{
    extern __shared__ char smem[];
    const uint32_t sb = smem_u32(smem);
    const int tid = threadIdx.x;
    const int grp = tid >> 8;
    const int gtid = tid & 255;
    const int gwid = gtid >> 5;

    // ---------- one-time: stage W / biases ----------
    for (int e = tid; e < 1088; e += NTHREADS)
        CP16(sb + OFF_W1H + e * 16, (const char*)g_W1ph + e * 16, 16);
    for (int e = tid; e < 1088; e += NTHREADS)
        CP16(sb + OFF_W1L + e * 16, (const char*)g_W1pl + e * 16, 16);
    for (int e = tid; e < 1152; e += NTHREADS)
        CP16(sb + OFF_W2H + e * 16, (const char*)g_W2ph + e * 16, 16);
    for (int e = tid; e < 1152; e += NTHREADS)
        CP16(sb + OFF_W2L + e * 16, (const char*)g_W2pl + e * 16, 16);
    for (int e = tid; e < 256; e += NTHREADS)
        CP16(sb + OFF_BB1 + e * 16, (const char*)g_Bb1 + e * 16, 16);
    for (int e = tid; e < 128; e += NTHREADS)
        CP16(sb + OFF_BB2 + e * 16, (const char*)g_Bb2 + e * 16, 16);
    if (tid < 256)
        ((__half*)(smem + OFF_ONES))[tid] =
            __float2half_rn(((tid & 15) < 2) ? 1.0f : 0.0f);

    __half* W1h = (__half*)(smem + OFF_W1H);
    __half* W1l = (__half*)(smem + OFF_W1L);
    __half* W2h = (__half*)(smem + OFF_W2H);
    __half* W2l = (__half*)(smem + OFF_W2L);
    __half* sBb1 = (__half*)(smem + OFF_BB1);
    __half* sBb2 = (__half*)(smem + OFF_BB2);
    __half* sOnes = (__half*)(smem + OFF_ONES);

    char* gbp = smem + OFF_GRP + grp * GRP_BYTES;
    const uint32_t gb = sb + OFF_GRP + grp * GRP_BYTES;
    __half* A1h = (__half*)(gbp + G_A);
    __half* A1l = (__half*)(gbp + G_A + 9216);
    float* sH   = (float*)(gbp + G_SH);
    float* sOut = (float*)(gbp + G_SH);
    float* sXs  = (float*)(gbp + G_SXS);

    const long long ntiles = ((long long)N + OUT_TILE - 1) / OUT_TILE;
    const long long stride = (long long)gridDim.x * 2;
    long long tile = (long long)blockIdx.x * 2 + grp;
    int p = 0;

    // ---------- prologue: first tile's x + dinv ----------
    if (tile < ntiles) {
        long long base = tile * OUT_TILE;
        for (int e = gtid; e < XROWS * 16; e += 256) {
            int t = e >> 4, q = e & 15;
            long long node = base - 2 + t;
            bool ok = (node >= 0 && node < (long long)N);
            const float* src = ok ? (x + node * 64 + q * 4) : x;
            CP16(gb + G_SXS + (uint32_t)(t * 272 + q * 16), src, ok ? 16 : 0);
        }
        if (gtid < 68) {
            long long node = base - 2 + gtid;
            float v = 0.0f;
            if (node >= 0 && node < (long long)N)
                v = (node == 0 || node == (long long)N - 1)
                    ? 0.70710678118654752f : 0.57735026918962576f;
            ((float*)(gbp + G_SDV))[gtid] = v;
        }
    }
    CP_COMMIT();
    CP_WAIT0();
    __syncthreads();

    // ---------- persistent tile loop ----------
    for (; tile < ntiles; tile += stride) {
        const long long base = tile * OUT_TILE;
        float* sdv = (float*)(gbp + G_SDV + p * 288);

        // ---- stencil1 (float4: 4 rows x 4 cols per task, 256 tasks) ----
        {
            int j0 = (gtid >> 4) * 4, k0 = (gtid & 15) * 4;
            float4 v[6];
            #pragma unroll
            for (int i = 0; i < 6; i++)            // j0+5 <= 65 in-bounds
                v[i] = *(float4*)&sXs[(j0 + i) * LDX + k0];
            #pragma unroll
            for (int rr = 0; rr < 4; rr++) {
                int j = j0 + rr;
                float d0 = sdv[j], d1 = sdv[j + 1], d2 = sdv[j + 2];
                float4 z;
                z.x = d1 * (d0 * v[rr].x + d1 * v[rr + 1].x + d2 * v[rr + 2].x);
                z.y = d1 * (d0 * v[rr].y + d1 * v[rr + 1].y + d2 * v[rr + 2].y);
                z.z = d1 * (d0 * v[rr].z + d1 * v[rr + 1].z + d2 * v[rr + 2].z);
                z.w = d1 * (d0 * v[rr].w + d1 * v[rr + 1].w + d2 * v[rr + 2].w);
                uint2 phi, plo;
                split4_pack(z, phi, plo);
                *(uint2*)&A1h[j * LDA1 + k0] = phi;
                *(uint2*)&A1l[j * LDA1 + k0] = plo;
            }
        }
        GBAR();

        // ---- prefetch next tile's x + dinv ----
        {
            long long nt2 = tile + stride;
            if (nt2 < ntiles) {
                long long nbase = nt2 * OUT_TILE;
                for (int e = gtid; e < XROWS * 16; e += 256) {
                    int t = e >> 4, q = e & 15;
                    long long node = nbase - 2 + t;
                    bool ok = (node >= 0 && node < (long long)N);
                    const float* src = ok ? (x + node * 64 + q * 4) : x;
                    CP16(gb + G_SXS + (uint32_t)(t * 272 + q * 16), src, ok ? 16 : 0);
                }
                if (gtid < 68) {
                    long long node = nbase - 2 + gtid;
                    float v = 0.0f;
                    if (node >= 0 && node < (long long)N)
                        v = (node == 0 || node == (long long)N - 1)
                            ? 0.70710678118654752f : 0.57735026918962576f;
                    ((float*)(gbp + G_SDV + (p ^ 1) * 288))[gtid] = v;
                }
            }
            CP_COMMIT();
        }

        // ---- MMA1 (8 warps, 4 colgroups x 2 rowgroups): sH = relu(A1@W1+b1) ----
        {
            const int cg = gwid & 3, rg = gwid >> 2;
            wmma::fragment<wmma::matrix_a, 16, 16, 16, __half, wmma::row_major> ah, al;
            wmma::fragment<wmma::matrix_b, 16, 16, 16, __half, wmma::row_major> bh[2], bl[2];
            wmma::fragment<wmma::accumulator, 16, 16, 16, float> acc[2][2];
            #pragma unroll
            for (int r = 0; r < 2; r++)
                #pragma unroll
                for (int c = 0; c < 2; c++) wmma::fill_fragment(acc[r][c], 0.0f);

            wmma::load_matrix_sync(ah, sOnes, 16);
            #pragma unroll
            for (int c = 0; c < 2; c++)
                wmma::load_matrix_sync(bh[c], sBb1 + (cg * 2 + c) * 16, 128);
            #pragma unroll
            for (int r = 0; r < 2; r++)
                #pragma unroll
                for (int c = 0; c < 2; c++)
                    wmma::mma_sync(acc[r][c], ah, bh[c], acc[r][c]);

            #pragma unroll
            for (int k = 0; k < 4; k++) {
                #pragma unroll
                for (int c = 0; c < 2; c++) {
                    wmma::load_matrix_sync(bh[c], W1h + (k * 16) * LDW1 + (cg * 2 + c) * 16, LDW1);
                    wmma::load_matrix_sync(bl[c], W1l + (k * 16) * LDW1 + (cg * 2 + c) * 16, LDW1);
                }
                #pragma unroll
                for (int r = 0; r < 2; r++) {
                    wmma::load_matrix_sync(ah, A1h + ((rg * 2 + r) * 16) * LDA1 + k * 16, LDA1);
                    wmma::load_matrix_sync(al, A1l + ((rg * 2 + r) * 16) * LDA1 + k * 16, LDA1);
                    #pragma unroll
                    for (int c = 0; c < 2; c++) {
                        wmma::mma_sync(acc[r][c], ah, bh[c], acc[r][c]);
                        wmma::mma_sync(acc[r][c], ah, bl[c], acc[r][c]);
                        wmma::mma_sync(acc[r][c], al, bh[c], acc[r][c]);
                    }
                }
            }
            #pragma unroll
            for (int r = 0; r < 2; r++)
                #pragma unroll
                for (int c = 0; c < 2; c++) {
                    #pragma unroll
                    for (int i = 0; i < acc[r][c].num_elements; i++)
                        acc[r][c].x[i] = fmaxf(acc[r][c].x[i], 0.0f);
                    wmma::store_matrix_sync(
                        sH + ((rg * 2 + r) * 16) * LDH + (cg * 2 + c) * 16,
                        acc[r][c], LDH, wmma::mem_row_major);
                }
        }
        GBAR();          // sH ready; A1 dead (A2 chunk buffers may overwrite)

        // ---- stencil2 chunk producer (float4: 2 rows x 4 cols, 256 tasks) ----
        auto stencil2_chunk = [&](int c, int b) {
            __half* bufh = (__half*)(gbp + G_A + b * 10240);
            __half* bufl = (__half*)(gbp + G_A + b * 10240 + 5120);
            int kc = c * 32;
            int r0 = (gtid >> 3) * 2, kq = (gtid & 7) * 4;
            float4 v[4];
            #pragma unroll
            for (int i = 0; i < 4; i++)
                v[i] = (r0 + i <= 63) ? *(float4*)&sH[(r0 + i) * LDH + kc + kq]
                                      : make_float4(0.f, 0.f, 0.f, 0.f);
            #pragma unroll
            for (int rr = 0; rr < 2; rr++) {
                int r = r0 + rr;
                float4 z = make_float4(0.f, 0.f, 0.f, 0.f);
                if (r <= 61) {
                    float d1 = sdv[r + 1], d2 = sdv[r + 2], d3 = sdv[r + 3];
                    z.x = d2 * (d1 * v[rr].x + d2 * v[rr + 1].x + d3 * v[rr + 2].x);
                    z.y = d2 * (d1 * v[rr].y + d2 * v[rr + 1].y + d3 * v[rr + 2].y);
                    z.z = d2 * (d1 * v[rr].z + d2 * v[rr + 1].z + d3 * v[rr + 2].z);
                    z.w = d2 * (d1 * v[rr].w + d2 * v[rr + 1].w + d3 * v[rr + 2].w);
                }
                uint2 phi, plo;
                split4_pack(z, phi, plo);
                *(uint2*)&bufh[r * LDA2C + kq] = phi;
                *(uint2*)&bufl[r * LDA2C + kq] = plo;
            }
        };

        // ---- chunk-pipelined stencil2 / MMA2 (8 warps, 4 col x 2 row) ----
        wmma::fragment<wmma::accumulator, 16, 16, 16, float> acc2[2];
        wmma::fill_fragment(acc2[0], 0.0f);
        wmma::fill_fragment(acc2[1], 0.0f);
        const int c2 = (gwid & 3) * 16, rs0 = (gwid >> 2) * 2;
        {
            wmma::fragment<wmma::matrix_a, 16, 16, 16, __half, wmma::row_major> aon;
            wmma::fragment<wmma::matrix_b, 16, 16, 16, __half, wmma::row_major> bb;
            wmma::load_matrix_sync(aon, sOnes, 16);
            wmma::load_matrix_sync(bb, sBb2 + c2, 64);
            wmma::mma_sync(acc2[0], aon, bb, acc2[0]);
            wmma::mma_sync(acc2[1], aon, bb, acc2[1]);
        }

        stencil2_chunk(0, 0);
        GBAR();

        #pragma unroll
        for (int c = 0; c < 4; c++) {
            if (c < 3) stencil2_chunk(c + 1, (c + 1) & 1);
            {
                __half* bufh = (__half*)(gbp + G_A + (c & 1) * 10240);
                __half* bufl = (__half*)(gbp + G_A + (c & 1) * 10240 + 5120);
                wmma::fragment<wmma::matrix_a, 16, 16, 16, __half, wmma::row_major> ah, al;
                wmma::fragment<wmma::matrix_b, 16, 16, 16, __half, wmma::row_major> bh, bl;
                #pragma unroll
                for (int s = 0; s < 2; s++) {
                    wmma::load_matrix_sync(bh, W2h + (c * 32 + s * 16) * LDW2 + c2, LDW2);
                    wmma::load_matrix_sync(bl, W2l + (c * 32 + s * 16) * LDW2 + c2, LDW2);
                    #pragma unroll
                    for (int r = 0; r < 2; r++) {
                        wmma::load_matrix_sync(ah, bufh + ((rs0 + r) * 16) * LDA2C + s * 16, LDA2C);
                        wmma::load_matrix_sync(al, bufl + ((rs0 + r) * 16) * LDA2C + s * 16, LDA2C);
                        wmma::mma_sync(acc2[r], ah, bh, acc2[r]);
                        wmma::mma_sync(acc2[r], ah, bl, acc2[r]);
                        wmma::mma_sync(acc2[r], al, bh, acc2[r]);
                    }
                }
            }
            if (c == 3) CP_WAIT0();      // next-tile x landed
            GBAR();
        }

        // ---- store: rows <48 direct; rows 48..61 staged ----
        if (base + OUT_TILE <= (long long)N) {
            #pragma unroll
            for (int r = 0; r < 2; r++) {
                int row0 = (rs0 + r) * 16;
                if (row0 < 48)
                    wmma::store_matrix_sync(out + (base + row0) * 64 + c2,
                                            acc2[r], 64, wmma::mem_row_major);
                else
                    wmma::store_matrix_sync(sOut + c2, acc2[r], LDO,
                                            wmma::mem_row_major);
            }
            GBAR();
            for (int e = gtid; e < 14 * 16; e += 256) {
                int r = e >> 4, q = e & 15;
                *(float4*)(out + (base + 48 + r) * 64 + q * 4) =
                    *(float4*)&sOut[r * LDO + q * 4];
            }
        } else {
            wmma::store_matrix_sync(sOut + (rs0 * 16) * LDO + c2, acc2[0], LDO,
                                    wmma::mem_row_major);
            wmma::store_matrix_sync(sOut + ((rs0 + 1) * 16) * LDO + c2, acc2[1], LDO,
                                    wmma::mem_row_major);
            GBAR();
            for (int e = gtid; e < 62 * 16; e += 256) {
                int r = e >> 4, q = e & 15;
                long long node = base + r;
                if (node < (long long)N)
                    *(float4*)(out + node * 64 + q * 4) =
                        *(float4*)&sOut[r * LDO + q * 4];
            }
        }
        p ^= 1;
    }
}

extern "C" void kernel_launch(void* const* d_in, const int* in_sizes, int n_in,
                              void* d_out, int out_size)
{
    const float* x  = (const float*)d_in[0];
    const float* W1 = (const float*)d_in[2];
    const float* b1 = (const float*)d_in[3];
    const float* W2 = (const float*)d_in[4];
    const float* b2 = (const float*)d_in[5];
    float* out = (float*)d_out;

    int N = in_sizes[0] / 64;

    int dev = 0, sms = 148;
    cudaGetDevice(&dev);
    cudaDeviceGetAttribute(&sms, cudaDevAttrMultiProcessorCount, dev);

    gcn_prep<<<32, 256>>>(W1, b1, W2, b2);

    cudaFuncSetAttribute(gcn_main,
                         cudaFuncAttributeMaxDynamicSharedMemorySize,
                         SMEM_BYTES);
    gcn_main<<<sms, NTHREADS, SMEM_BYTES>>>(x, out, N);
}